// round 16
// baseline (speedup 1.0000x reference)
#include <cuda_runtime.h>
#include <cstdint>
#include <climits>

#define BATCH 4
#define T 1024
#define D 64
#define H 2
#define HD 32
#define DFF 256
#define NL 4
#define VOCAB 8192
#define BT (BATCH*T)

// ---------------- device scratch (no allocs allowed) ----------------
__device__ __align__(16) int8_t  g_x[BT*D];
__device__ __align__(16) int8_t  g_h[BT*D];
__device__ __align__(16) int8_t  g_q[BT*D];
__device__ __align__(16) int8_t  g_k[BT*D];
__device__ __align__(16) int8_t  g_a[BT*D];
__device__ __align__(16) int8_t  g_vt[BATCH*H*(T/4)*HD*4];
__device__ __align__(16) int8_t  g_wq[NL*D*D], g_wk[NL*D*D], g_wv[NL*D*D], g_wo[NL*D*D];
__device__ __align__(16) int8_t  g_wup[NL*DFF*D], g_wdn[NL*D*DFF];
__device__ __align__(16) int     g_gattn[NL*D], g_gff[NL*D], g_gfin[D];
__device__ __align__(16) int8_t  g_ehi[VOCAB*D];
__device__ __align__(16) uint8_t g_elo[VOCAB*D];

// ---------------- helpers ----------------
__device__ __forceinline__ int wrap8(int v){ return (int)(signed char)(v & 0xff); }
__device__ __forceinline__ int clampi(int v,int lo,int hi){ return min(max(v,lo),hi); }
__device__ __forceinline__ int gammaq(float w){
    float c = fminf(fmaxf(w,-2.f),2.f);
    float r = rintf(__fmul_rn(c,1024.f));
    return clampi((int)r,-32768,32767);
}
__device__ __forceinline__ void rms_pair(int x0,int x1,int g0,int g1,int& y0,int& y1){
    int ss = x0*x0 + x1*x1;
    #pragma unroll
    for(int o=16;o>0;o>>=1) ss += __shfl_xor_sync(0xffffffffu, ss, o);
    int mean_sq = ss >> 6;
    int lut = min(mean_sq >> 6, 255);
    float bc = (float)(lut*64 + 32);
    int inv = clampi((int)rintf(__fdiv_rn(16384.f, __fsqrt_rn(bc))), 0, 16383);
    int p0 = (x0*inv) >> 8, p1 = (x1*inv) >> 8;
    y0 = clampi((int)floorf(__fmul_rn(__fmul_rn((float)p0,(float)g0), 0.0009765625f)),-128,127);
    y1 = clampi((int)floorf(__fmul_rn(__fmul_rn((float)p1,(float)g1), 0.0009765625f)),-128,127);
}
__device__ __forceinline__ void mma_s8s8(int* d, const int* a, const int* b){
    asm("mma.sync.aligned.m16n8k32.row.col.s32.s8.s8.s32 "
        "{%0,%1,%2,%3},{%4,%5,%6,%7},{%8,%9},{%0,%1,%2,%3};"
        : "+r"(d[0]),"+r"(d[1]),"+r"(d[2]),"+r"(d[3])
        : "r"(a[0]),"r"(a[1]),"r"(a[2]),"r"(a[3]),"r"(b[0]),"r"(b[1]));
}
__device__ __forceinline__ void mma_s8u8(int* d, const int* a, const int* b){
    asm("mma.sync.aligned.m16n8k32.row.col.s32.s8.u8.s32 "
        "{%0,%1,%2,%3},{%4,%5,%6,%7},{%8,%9},{%0,%1,%2,%3};"
        : "+r"(d[0]),"+r"(d[1]),"+r"(d[2]),"+r"(d[3])
        : "r"(a[0]),"r"(a[1]),"r"(a[2]),"r"(a[3]),"r"(b[0]),"r"(b[1]));
}
__device__ __forceinline__ void mma_u8s8(int* d, const unsigned* a, const int* b){
    asm("mma.sync.aligned.m16n8k32.row.col.s32.u8.s8.s32 "
        "{%0,%1,%2,%3},{%4,%5,%6,%7},{%8,%9},{%0,%1,%2,%3};"
        : "+r"(d[0]),"+r"(d[1]),"+r"(d[2]),"+r"(d[3])
        : "r"(a[0]),"r"(a[1]),"r"(a[2]),"r"(a[3]),"r"(b[0]),"r"(b[1]));
}
__device__ __forceinline__ int ea_of_idx(int l){
    return (l<16) ? l : (l<21 ? 64+11*(l-21) : (l<=24 ? 256+64*(l-24) : 0));
}
// exact score: floor(rn(d*45)*2^-8); int shortcut lossless below 2^24
__device__ __forceinline__ int score1(int d){
    int v = d*45;
    if(abs(v) < (1<<24)) return v >> 8;
    return (int)floorf(__fmul_rn(__int2float_rn(v), 0.00390625f));
}
__device__ __forceinline__ void score4m(const int* d, int c0, int r0, int r8, int* s){
    s[0] = score1(d[0]); s[1] = score1(d[1]);
    s[2] = score1(d[2]); s[3] = score1(d[3]);
    if(c0   > r0) s[0] = -32767;
    if(c0+1 > r0) s[1] = -32767;
    if(c0   > r8) s[2] = -32767;
    if(c0+1 > r8) s[3] = -32767;
}
__device__ __forceinline__ void score4n(const int* d, int* s){
    s[0] = score1(d[0]); s[1] = score1(d[1]);
    s[2] = score1(d[2]); s[3] = score1(d[3]);
}

// ---------------- merged prep ----------------
__global__ void prep_all(const float* qw, const float* kw, const float* vw,
                         const float* ow, const float* up, const float* dn,
                         const float* tok_emb, const float* attn_nw,
                         const float* ff_nw, const float* fin_nw){
    int m = blockIdx.x;
    if(m < 24){
        const float* src; int8_t* dst; int n;
        if(m < 16){
            int l = m >> 2, wsel = m & 3; n = D*D;
            const float* bases[4] = {qw,kw,vw,ow};
            int8_t* dsts[4] = {g_wq,g_wk,g_wv,g_wo};
            src = bases[wsel] + l*n; dst = dsts[wsel] + l*n;
        } else if(m < 20){ int l=m-16; n=DFF*D; src=up+l*n; dst=g_wup+l*n; }
        else             { int l=m-20; n=D*DFF; src=dn+l*n; dst=g_wdn+l*n; }

        __shared__ float red[256];
        float s = 0.f;
        for(int i=threadIdx.x;i<n;i+=256) s += fabsf(src[i]);
        red[threadIdx.x]=s; __syncthreads();
        for(int o=128;o>0;o>>=1){ if(threadIdx.x<o) red[threadIdx.x]+=red[threadIdx.x+o]; __syncthreads(); }
        float scale = fmaxf(__fdiv_rn(red[0], (float)n), 1e-5f);
        for(int i=threadIdx.x;i<n;i+=256){
            float t = rintf(__fdiv_rn(src[i], scale));
            t = fminf(fmaxf(t,-1.f),1.f);
            dst[i] = (int8_t)(int)t;
        }
        return;
    }
    int i = (m-24)*256 + threadIdx.x;
    if(i < VOCAB*D){
        float r = rintf(__fmul_rn(tok_emb[i],1024.f));
        int q = clampi((int)r,-32768,32767);
        g_ehi[i] = (int8_t)(q >> 8);
        g_elo[i] = (uint8_t)(q & 0xff);
    }
    if(m == 24){
        int t=threadIdx.x;
        for(int j=t;j<NL*D;j+=256){
            g_gattn[j] = gammaq(attn_nw[j]);
            g_gff[j]   = gammaq(ff_nw[j]);
        }
        if(t<D) g_gfin[t] = gammaq(fin_nw[t]);
    }
}

// ---- shared qkv tail ----
__device__ __forceinline__ void qkv_tail(const uint8_t* sx2, uint8_t* shb, int layer,
                                         int bt0, int warp, int lane, int g, int tg){
    const int* gm = g_gattn + layer*D;
    #pragma unroll
    for(int t=0;t<2;t++){
        int tok = 2*warp + t;
        int x0 = (int)(int8_t)sx2[tok*68 + 2*lane];
        int x1 = (int)(int8_t)sx2[tok*68 + 2*lane+1];
        int y0,y1;
        rms_pair(x0,x1,gm[2*lane],gm[2*lane+1],y0,y1);
        shb[tok*68 + 2*lane]   = (uint8_t)(y0 & 0xff);
        shb[tok*68 + 2*lane+1] = (uint8_t)(y1 & 0xff);
    }
    __syncthreads();
    const int* shi = (const int*)shb;
    int a[2][4];
    #pragma unroll
    for(int kc=0;kc<2;kc++){
        a[kc][0] = shi[g*17     + kc*8 + tg];
        a[kc][1] = shi[(g+8)*17 + kc*8 + tg];
        a[kc][2] = shi[g*17     + kc*8 + 4 + tg];
        a[kc][3] = shi[(g+8)*17 + kc*8 + 4 + tg];
    }
    const int* wq = (const int*)(g_wq + layer*D*D);
    const int* wk = (const int*)(g_wk + layer*D*D);
    const int* wv = (const int*)(g_wv + layer*D*D);
    #pragma unroll
    for(int nt=0;nt<3;nt++){
        const int* wb = (nt==0) ? wq : (nt==1 ? wk : wv);
        int c = warp*8 + g;
        int d[4] = {0,0,0,0};
        #pragma unroll
        for(int kc=0;kc<2;kc++){
            int b[2] = { wb[c*16 + kc*8 + tg], wb[c*16 + kc*8 + 4 + tg] };
            mma_s8s8(d, a[kc], b);
        }
        int o0 = warp*8 + 2*tg;
        int v0 = clampi(d[0]>>6,-128,127), v1 = clampi(d[1]>>6,-128,127);
        int v2 = clampi(d[2]>>6,-128,127), v3 = clampi(d[3]>>6,-128,127);
        if(nt < 2){
            int8_t* dst = (nt==0) ? g_q : g_k;
            *(uint16_t*)(dst + (bt0+g)*64   + o0) = (uint16_t)((v0&0xff) | ((v1&0xff)<<8));
            *(uint16_t*)(dst + (bt0+g+8)*64 + o0) = (uint16_t)((v2&0xff) | ((v3&0xff)<<8));
        } else {
            int bt_a = bt0 + g, bt_b = bt0 + g + 8;
            int bsel = bt_a >> 10;
            int ta = bt_a & (T-1), tb = bt_b & (T-1);
            int hh = o0 >> 5, hd = o0 & 31;
            int8_t* vtb = g_vt + (bsel*2 + hh)*((T/4)*HD*4);
            vtb[(ta>>2)*128 + hd*4     + (ta&3)] = (int8_t)v0;
            vtb[(ta>>2)*128 + (hd+1)*4 + (ta&3)] = (int8_t)v1;
            vtb[(tb>>2)*128 + hd*4     + (tb&3)] = (int8_t)v2;
            vtb[(tb>>2)*128 + (hd+1)*4 + (tb&3)] = (int8_t)v3;
        }
    }
}

// ---------------- embed + qkv(0) ----------------
__global__ __launch_bounds__(256) void embed_qkv_kernel(const int* tokens,
                                                        const float* tok_emb,
                                                        const float* pos_emb){
    __shared__ uint8_t sx2[16*68];
    __shared__ uint8_t shb[16*68];
    int tid = threadIdx.x, warp = tid>>5, lane = tid&31;
    int g = lane>>2, tg = lane&3;
    int bt0 = blockIdx.x*16;
    for(int idx = tid; idx < 16*64; idx += 256){
        int bt = bt0 + (idx>>6), d = idx & 63;
        int t = bt & (T-1);
        int tok = tokens[bt];
        int tq = clampi((int)rintf(__fmul_rn(tok_emb[tok*D+d],1024.f)),-32768,32767);
        int pq = clampi((int)rintf(__fmul_rn(pos_emb[t*D+d],1024.f)),-32768,32767);
        int xv = wrap8((tq+pq) >> 3);
        g_x[bt*D + d] = (int8_t)xv;
        sx2[(idx>>6)*68 + d] = (uint8_t)(xv & 0xff);
    }
    __syncthreads();
    qkv_tail(sx2, shb, 0, bt0, warp, lane, g, tg);
}

// ---------------- attention: two-pass MMA scores (ILP x4) + LUT softmax + dual-acc AV ----------------
#define SPB_PITCH 1040

__global__ __launch_bounds__(256) void attn_fused_kernel(){
    __shared__ uint8_t sP[16*SPB_PITCH];
    __shared__ uint8_t plut[16*32];
    __shared__ int rowmax[16];
    __shared__ int rowsum[16];
    __shared__ int sred[16*36];

    int tid = threadIdx.x, warp = tid>>5, lane = tid&31;
    int g = lane>>2, tg = lane&3;
    int qt = gridDim.x - 1 - blockIdx.x;     // LPT
    int bh = blockIdx.y, b = bh>>1, h = bh&1;
    int qb = qt*16, base = b*T;
    int KN = qb + 16, nch = KN >> 3;
    int KNpad = (KN + 31) & ~31;

    if(tid < 16){ rowmax[tid] = INT_MIN; rowsum[tid] = 0; }
    __syncthreads();

    const int* qp = (const int*)g_q;
    int aq[4];
    aq[0] = qp[(base+qb+g)*16   + h*8 + tg];
    aq[1] = qp[(base+qb+g+8)*16 + h*8 + tg];
    aq[2] = qp[(base+qb+g)*16   + h*8 + 4 + tg];
    aq[3] = qp[(base+qb+g+8)*16 + h*8 + 4 + tg];
    const int* kp = (const int*)g_k;
    int r0 = qb + g, r8 = qb + g + 8;

    // ---- pass A: row maxima (ILP x4) ----
    {
        int mg = INT_MIN, mg8 = INT_MIN;
        for(int c = warp; c < nch; c += 32){
            int d4[4][4];
            bool hasu[4];
            #pragma unroll
            for(int u=0;u<4;u++){
                int cc = c + u*8;
                hasu[u] = cc < nch;
                d4[u][0]=d4[u][1]=d4[u][2]=d4[u][3]=0;
                if(hasu[u]){
                    int k0 = cc*8;
                    int bv[2] = { kp[(base+k0+g)*16 + h*8 + tg],
                                  kp[(base+k0+g)*16 + h*8 + 4 + tg] };
                    mma_s8s8(d4[u], aq, bv);
                }
            }
            #pragma unroll
            for(int u=0;u<4;u++){
                if(!hasu[u]) break;
                int kk = (c + u*8)*8;
                int s[4];
                if(kk + 7 <= qb) score4n(d4[u], s);
                else             score4m(d4[u], kk + 2*tg, r0, r8, s);
                mg  = max(mg,  max(s[0],s[1]));
                mg8 = max(mg8, max(s[2],s[3]));
            }
        }
        mg  = max(mg,  __shfl_xor_sync(0xffffffffu, mg , 1));
        mg  = max(mg,  __shfl_xor_sync(0xffffffffu, mg , 2));
        mg8 = max(mg8, __shfl_xor_sync(0xffffffffu, mg8, 1));
        mg8 = max(mg8, __shfl_xor_sync(0xffffffffu, mg8, 2));
        if(tg == 0){
            atomicMax(&rowmax[g],   mg);
            atomicMax(&rowmax[g+8], mg8);
        }
    }
    __syncthreads();

    // ---- pass B: recompute -> idx bytes + ea-sums (ILP x4) ----
    {
        int m_g = rowmax[g], m_g8 = rowmax[g+8];
        int ea_l = ea_of_idx(lane);
        int su_g = 0, su_g8 = 0;
        for(int c = warp; c < nch; c += 32){
            int d4[4][4];
            bool hasu[4];
            #pragma unroll
            for(int u=0;u<4;u++){
                int cc = c + u*8;
                hasu[u] = cc < nch;
                d4[u][0]=d4[u][1]=d4[u][2]=d4[u][3]=0;
                if(hasu[u]){
                    int k0 = cc*8;
                    int bv[2] = { kp[(base+k0+g)*16 + h*8 + tg],
                                  kp[(base+k0+g)*16 + h*8 + 4 + tg] };
                    mma_s8s8(d4[u], aq, bv);
                }
            }
            #pragma unroll
            for(int u=0;u<4;u++){
                if(!hasu[u]) break;
                int kk = (c + u*8)*8;
                int c0 = kk + 2*tg;
                int s[4];
                if(kk + 7 <= qb) score4n(d4[u], s);
                else             score4m(d4[u], c0, r0, r8, s);
                int i0 = max(s[0] - m_g  + 24, 0);
                int i1 = max(s[1] - m_g  + 24, 0);
                int i2 = max(s[2] - m_g8 + 24, 0);
                int i3 = max(s[3] - m_g8 + 24, 0);
                su_g  += __shfl_sync(0xffffffffu, ea_l, i0) + __shfl_sync(0xffffffffu, ea_l, i1);
                su_g8 += __shfl_sync(0xffffffffu, ea_l, i2) + __shfl_sync(0xffffffffu, ea_l, i3);
                *(uint16_t*)&sP[g*SPB_PITCH + c0]     = (uint16_t)(i0 | (i1<<8));
                *(uint16_t*)&sP[(g+8)*SPB_PITCH + c0] = (uint16_t)(i2 | (i3<<8));
            }
        }
        su_g  += __shfl_xor_sync(0xffffffffu, su_g, 1);
        su_g  += __shfl_xor_sync(0xffffffffu, su_g, 2);
        su_g8 += __shfl_xor_sync(0xffffffffu, su_g8, 1);
        su_g8 += __shfl_xor_sync(0xffffffffu, su_g8, 2);
        if(tg == 0){
            atomicAdd(&rowsum[g],   su_g);
            atomicAdd(&rowsum[g+8], su_g8);
        }
    }
    if(KNpad > KN && tid < 64){
        int row = tid >> 2, wsel = tid & 3;
        *(unsigned*)&sP[row*SPB_PITCH + KN + wsel*4] = 0;
    }
    __syncthreads();

    // ---- per-row prob LUT ----
    for(int e = tid; e < 512; e += 256){
        int row = e>>5, l = e&31;
        int p = 0;
        if(l <= 24){
            int ea = ea_of_idx(l);
            if(ea > 0){
                float sf = (float)max(rowsum[row], 1);
                p = clampi((int)rintf(__fmul_rn(__fdiv_rn((float)ea, sf), 255.f)), 0, 255);
            }
        }
        plut[row*32 + l] = (uint8_t)p;
    }
    __syncthreads();

    // ---- idx -> prob, word-wise in place ----
    #pragma unroll
    for(int rr = 0; rr < 2; rr++){
        int r = 2*warp + rr;
        const uint8_t* pl = plut + r*32;
        for(int wd = lane; wd < (KNpad>>2); wd += 32){
            unsigned v = *(unsigned*)&sP[r*SPB_PITCH + wd*4];
            unsigned o =  (unsigned)pl[v & 31]
                       | ((unsigned)pl[(v>>8)  & 31] << 8)
                       | ((unsigned)pl[(v>>16) & 31] << 16)
                       | ((unsigned)pl[(v>>24) & 31] << 24);
            *(unsigned*)&sP[r*SPB_PITCH + wd*4] = o;
        }
    }
    __syncthreads();

    // ---- AV via u8 x s8 MMA, dual accumulators ----
    int nt = warp & 3, half = warp >> 2;
    int dim = nt*8 + g;
    const int* vt = (const int*)(g_vt) + bh*((T/4)*HD);
    int da0[4] = {0,0,0,0}, da1[4] = {0,0,0,0};
    int nch32 = KNpad >> 5;
    for(int c32 = half; c32 < nch32; c32 += 4){
        {
            unsigned A[4];
            A[0] = *(unsigned*)&sP[g*SPB_PITCH     + c32*32 + tg*4];
            A[1] = *(unsigned*)&sP[(g+8)*SPB_PITCH + c32*32 + tg*4];
            A[2] = *(unsigned*)&sP[g*SPB_PITCH     + c32*32 + 16 + tg*4];
            A[3] = *(unsigned*)&sP[(g+8)*SPB_PITCH + c32*32 + 16 + tg*4];
            int Bv[2];
            Bv[0] = vt[(c32*8 + tg)*32 + dim];
            Bv[1] = vt[(c32*8 + 4 + tg)*32 + dim];
            mma_u8s8(da0, A, Bv);
        }
        int c2 = c32 + 2;
        if(c2 < nch32){
            unsigned A[4];
            A[0] = *(unsigned*)&sP[g*SPB_PITCH     + c2*32 + tg*4];
            A[1] = *(unsigned*)&sP[(g+8)*SPB_PITCH + c2*32 + tg*4];
            A[2] = *(unsigned*)&sP[g*SPB_PITCH     + c2*32 + 16 + tg*4];
            A[3] = *(unsigned*)&sP[(g+8)*SPB_PITCH + c2*32 + 16 + tg*4];
            int Bv[2];
            Bv[0] = vt[(c2*8 + tg)*32 + dim];
            Bv[1] = vt[(c2*8 + 4 + tg)*32 + dim];
            mma_u8s8(da1, A, Bv);
        }
    }
    int dacc[4];
    #pragma unroll
    for(int e=0;e<4;e++) dacc[e] = da0[e] + da1[e];

    if(half == 1){
        sred[g*36     + nt*8 + 2*tg]     = dacc[0];
        sred[g*36     + nt*8 + 2*tg + 1] = dacc[1];
        sred[(g+8)*36 + nt*8 + 2*tg]     = dacc[2];
        sred[(g+8)*36 + nt*8 + 2*tg + 1] = dacc[3];
    }
    __syncthreads();
    if(half == 0){
        int v0 = dacc[0] + sred[g*36     + nt*8 + 2*tg];
        int v1 = dacc[1] + sred[g*36     + nt*8 + 2*tg + 1];
        int v2 = dacc[2] + sred[(g+8)*36 + nt*8 + 2*tg];
        int v3 = dacc[3] + sred[(g+8)*36 + nt*8 + 2*tg + 1];
        int o0 = wrap8(v0>>8)&0xff, o1 = wrap8(v1>>8)&0xff;
        int o2 = wrap8(v2>>8)&0xff, o3 = wrap8(v3>>8)&0xff;
        *(uint16_t*)(g_a + (base+qb+g)*64   + h*32 + nt*8 + 2*tg) = (uint16_t)(o0 | (o1<<8));
        *(uint16_t*)(g_a + (base+qb+g+8)*64 + h*32 + nt*8 + 2*tg) = (uint16_t)(o2 | (o3<<8));
    }
}

// ---------------- fused oproj+res+rmsnorm+FFN+res, then qkv(layer+1) or final rmsnorm ----------------
__global__ __launch_bounds__(256) void ffn_qkv_kernel(int layer){
    __shared__ int      sa[16*17];
    __shared__ uint8_t  sxb[16*64];
    __shared__ uint8_t  shb[16*68];
    __shared__ uint8_t  sub[16*260];
    __shared__ uint8_t  sx2[16*68];
    int tid = threadIdx.x, warp = tid>>5, lane = tid&31;
    int g = lane>>2, tg = lane&3;
    int bt0 = blockIdx.x*16;

    {
        int tok = tid>>4, i = tid&15;
        sa[tok*17+i] = ((const int*)g_a)[(bt0+tok)*16 + i];
    }
    __syncthreads();

    {   // oproj + residual
        int a[2][4];
        #pragma unroll
        for(int kc=0;kc<2;kc++){
            a[kc][0] = sa[g*17     + kc*8 + tg];
            a[kc][1] = sa[(g+8)*17 + kc*8 + tg];
            a[kc][2] = sa[g*17     + kc*8 + 4 + tg];
            a[kc][3] = sa[(g+8)*17 + kc*8 + 4 + tg];
        }
        const int* wo = (const int*)(g_wo + layer*D*D);
        int c = warp*8 + g;
        int d[4] = {0,0,0,0};
        #pragma unroll
        for(int kc=0;kc<2;kc++){
            int b[2] = { wo[c*16 + kc*8 + tg], wo[c*16 + kc*8 + 4 + tg] };
            mma_s8s8(d, a[kc], b);
        }
        int o0 = warp*8 + 2*tg;
        int r0 = clampi(d[0]>>6,-128,127), r1 = clampi(d[1]>>6,-128,127);
        int r2 = clampi(d[2]>>6,-128,127), r3 = clampi(d[3]>>6,-128,127);
        sxb[g*64 + o0]       = (uint8_t)(wrap8((int)g_x[(bt0+g)*64 + o0]     + r0) & 0xff);
        sxb[g*64 + o0+1]     = (uint8_t)(wrap8((int)g_x[(bt0+g)*64 + o0+1]   + r1) & 0xff);
        sxb[(g+8)*64 + o0]   = (uint8_t)(wrap8((int)g_x[(bt0+g+8)*64 + o0]   + r2) & 0xff);
        sxb[(g+8)*64 + o0+1] = (uint8_t)(wrap8((int)g_x[(bt0+g+8)*64 + o0+1] + r3) & 0xff);
    }
    __syncthreads();

    {   // ffn rmsnorm
        const int* gm = g_gff + layer*D;
        #pragma unroll
        for(int t=0;t<2;t++){
            int tok = 2*warp + t;
            int x0 = (int)(int8_t)sxb[tok*64 + 2*lane];
            int x1 = (int)(int8_t)sxb[tok*64 + 2*lane+1];
            int y0,y1;
            rms_pair(x0,x1,gm[2*lane],gm[2*lane+1],y0,y1);
            shb[tok*68 + 2*lane]   = (uint8_t)(y0 & 0xff);
            shb[tok*68 + 2*lane+1] = (uint8_t)(y1 & 0xff);
        }
    }
    __syncthreads();

    {   // up + relu
        const int* shi = (const int*)shb;
        int a[2][4];
        #pragma unroll
        for(int kc=0;kc<2;kc++){
            a[kc][0] = shi[g*17     + kc*8 + tg];
            a[kc][1] = shi[(g+8)*17 + kc*8 + tg];
            a[kc][2] = shi[g*17     + kc*8 + 4 + tg];
            a[kc][3] = shi[(g+8)*17 + kc*8 + 4 + tg];
        }
        const int* wu = (const int*)(g_wup + layer*DFF*D);
        #pragma unroll
        for(int nt=0;nt<4;nt++){
            int colb = warp*32 + nt*8;
            int c = colb + g;
            int d[4] = {0,0,0,0};
            #pragma unroll
            for(int kc=0;kc<2;kc++){
                int b[2] = { wu[c*16 + kc*8 + tg], wu[c*16 + kc*8 + 4 + tg] };
                mma_s8s8(d, a[kc], b);
            }
            int c0 = colb + 2*tg;
            int u0 = max(clampi(d[0]>>6,-128,127),0), u1 = max(clampi(d[1]>>6,-128,127),0);
            int u2 = max(clampi(d[2]>>6,-128,127),0), u3 = max(clampi(d[3]>>6,-128,127),0);
            sub[g*260 + c0]       = (uint8_t)u0;
            sub[g*260 + c0+1]     = (uint8_t)u1;
            sub[(g+8)*260 + c0]   = (uint8_t)u2;
            sub[(g+8)*260 + c0+1] = (uint8_t)u3;
        }
    }
    __syncthreads();

    {   // down (K=256) + residual -> sx2, g_x
        const int* sui = (const int*)sub;
        const int* wd = (const int*)(g_wdn + layer*D*DFF);
        int c = warp*8 + g;
        int d[4] = {0,0,0,0};
        #pragma unroll
        for(int kc=0;kc<8;kc++){
            int a[4];
            a[0] = sui[g*65     + kc*8 + tg];
            a[1] = sui[(g+8)*65 + kc*8 + tg];
            a[2] = sui[g*65     + kc*8 + 4 + tg];
            a[3] = sui[(g+8)*65 + kc*8 + 4 + tg];
            int b[2] = { wd[c*64 + kc*8 + tg], wd[c*64 + kc*8 + 4 + tg] };
            mma_s8s8(d, a, b);
        }
        int o0 = warp*8 + 2*tg;
        int r0 = clampi(d[0]>>6,-128,127), r1 = clampi(d[1]>>6,-128,127);
        int r2 = clampi(d[2]>>6,-128,127), r3 = clampi(d[3]>>6,-128,127);
        int x0 = wrap8((int)(int8_t)sxb[g*64 + o0]       + r0);
        int x1 = wrap8((int)(int8_t)sxb[g*64 + o0+1]     + r1);
        int x2 = wrap8((int)(int8_t)sxb[(g+8)*64 + o0]   + r2);
        int x3 = wrap8((int)(int8_t)sxb[(g+8)*64 + o0+1] + r3);
        g_x[(bt0+g)*64 + o0]     = (int8_t)x0;
        g_x[(bt0+g)*64 + o0+1]   = (int8_t)x1;
        g_x[(bt0+g+8)*64 + o0]   = (int8_t)x2;
        g_x[(bt0+g+8)*64 + o0+1] = (int8_t)x3;
        sx2[g*68 + o0]       = (uint8_t)(x0 & 0xff);
        sx2[g*68 + o0+1]     = (uint8_t)(x1 & 0xff);
        sx2[(g+8)*68 + o0]   = (uint8_t)(x2 & 0xff);
        sx2[(g+8)*68 + o0+1] = (uint8_t)(x3 & 0xff);
    }
    __syncthreads();

    if(layer + 1 < NL){
        qkv_tail(sx2, shb, layer+1, bt0, warp, lane, g, tg);
    } else {
        const int* gm = g_gfin;
        #pragma unroll
        for(int t=0;t<2;t++){
            int tok = 2*warp + t;
            int x0 = (int)(int8_t)sx2[tok*68 + 2*lane];
            int x1 = (int)(int8_t)sx2[tok*68 + 2*lane+1];
            int y0,y1;
            rms_pair(x0,x1,gm[2*lane],gm[2*lane+1],y0,y1);
            g_h[(bt0+tok)*D + 2*lane]   = (int8_t)y0;
            g_h[(bt0+tok)*D + 2*lane+1] = (int8_t)y1;
        }
    }
}

// ---------------- logits via IMMA ----------------
__global__ __launch_bounds__(256) void logits_mma_kernel(float* __restrict__ out){
    int warp = threadIdx.x>>5, lane = threadIdx.x&31;
    int g = lane>>2, tg = lane&3;
    int vbase = blockIdx.x*256 + warp*32;
    int mbase = blockIdx.y*64;

    int bhi[4][2][2], blo[4][2][2];
    #pragma unroll
    for(int nt=0;nt<4;nt++){
        int col = vbase + nt*8 + g;
        const int8_t*  eh = g_ehi + col*64;
        const uint8_t* el = g_elo + col*64;
        #pragma unroll
        for(int kc=0;kc<2;kc++){
            bhi[nt][kc][0] = *(const int*)(eh + kc*32 + tg*4);
            bhi[nt][kc][1] = *(const int*)(eh + kc*32 + 16 + tg*4);
            blo[nt][kc][0] = *(const int*)(el + kc*32 + tg*4);
            blo[nt][kc][1] = *(const int*)(el + kc*32 + 16 + tg*4);
        }
    }
    #pragma unroll
    for(int mt=0;mt<4;mt++){
        int row0 = mbase + mt*16 + g;
        const int8_t* h0 = g_h + row0*64;
        const int8_t* h8 = g_h + (row0+8)*64;
        int a[2][4];
        #pragma unroll
        for(int kc=0;kc<2;kc++){
            a[kc][0] = *(const int*)(h0 + kc*32 + tg*4);
            a[kc][1] = *(const int*)(h8 + kc*32 + tg*4);
            a[kc][2] = *(const int*)(h0 + kc*32 + 16 + tg*4);
            a[kc][3] = *(const int*)(h8 + kc*32 + 16 + tg*4);
        }
        #pragma unroll
        for(int nt=0;nt<4;nt++){
            int dh[4]={0,0,0,0}, dl[4]={0,0,0,0};
            #pragma unroll
            for(int kc=0;kc<2;kc++){
                mma_s8s8(dh, a[kc], bhi[nt][kc]);
                mma_s8u8(dl, a[kc], blo[nt][kc]);
            }
            int col = vbase + nt*8 + 2*tg;
            float2 v0, v1;
            v0.x = __fmul_rn((float)(dh[0]*256+dl[0]), 1.220703125e-4f);
            v0.y = __fmul_rn((float)(dh[1]*256+dl[1]), 1.220703125e-4f);
            v1.x = __fmul_rn((float)(dh[2]*256+dl[2]), 1.220703125e-4f);
            v1.y = __fmul_rn((float)(dh[3]*256+dl[3]), 1.220703125e-4f);
            *(float2*)(out + (size_t)row0*VOCAB + col)     = v0;
            *(float2*)(out + (size_t)(row0+8)*VOCAB + col) = v1;
        }
    }
}

// ---------------- launch ----------------
extern "C" void kernel_launch(void* const* d_in, const int* in_sizes, int n_in,
                              void* d_out, int out_size){
    const int*   tokens  = (const int*)  d_in[0];
    const float* tok_emb = (const float*)d_in[1];
    const float* pos_emb = (const float*)d_in[2];
    const float* attn_nw = (const float*)d_in[3];
    const float* qw      = (const float*)d_in[4];
    const float* kw      = (const float*)d_in[5];
    const float* vw      = (const float*)d_in[6];
    const float* ow      = (const float*)d_in[7];
    const float* ff_nw   = (const float*)d_in[8];
    const float* up      = (const float*)d_in[9];
    const float* dn      = (const float*)d_in[10];
    const float* fin_nw  = (const float*)d_in[11];
    float* out = (float*)d_out;

    prep_all<<<24 + (VOCAB*D+255)/256, 256>>>(qw,kw,vw,ow,up,dn,
                                              tok_emb, attn_nw, ff_nw, fin_nw);
    embed_qkv_kernel<<<BT/16,256>>>(tokens, tok_emb, pos_emb);

    for(int l=0;l<NL;l++){
        attn_fused_kernel<<<dim3(T/16, BATCH*H),256>>>();
        ffn_qkv_kernel<<<BT/16,256>>>(l);
    }
    logits_mma_kernel<<<dim3(VOCAB/256, BT/64),256>>>(out);
}

// round 17
// speedup vs baseline: 1.0426x; 1.0426x over previous
#include <cuda_runtime.h>
#include <cstdint>
#include <climits>

#define BATCH 4
#define T 1024
#define D 64
#define H 2
#define HD 32
#define DFF 256
#define NL 4
#define VOCAB 8192
#define BT (BATCH*T)

// ---------------- device scratch (no allocs allowed) ----------------
__device__ __align__(16) int8_t  g_x[BT*D];
__device__ __align__(16) int8_t  g_h[BT*D];
__device__ __align__(16) int8_t  g_q[BT*D];
__device__ __align__(16) int8_t  g_k[BT*D];
__device__ __align__(16) int8_t  g_a[BT*D];
__device__ __align__(16) int8_t  g_vt[BATCH*H*(T/4)*HD*4];
__device__ __align__(16) int8_t  g_wq[NL*D*D], g_wk[NL*D*D], g_wv[NL*D*D], g_wo[NL*D*D];
__device__ __align__(16) int8_t  g_wup[NL*DFF*D], g_wdn[NL*D*DFF];
__device__ __align__(16) int     g_gattn[NL*D], g_gff[NL*D], g_gfin[D];
__device__ __align__(16) int8_t  g_ehi[VOCAB*D];
__device__ __align__(16) uint8_t g_elo[VOCAB*D];

// ---------------- helpers ----------------
__device__ __forceinline__ int wrap8(int v){ return (int)(signed char)(v & 0xff); }
__device__ __forceinline__ int clampi(int v,int lo,int hi){ return min(max(v,lo),hi); }
__device__ __forceinline__ int gammaq(float w){
    float c = fminf(fmaxf(w,-2.f),2.f);
    float r = rintf(__fmul_rn(c,1024.f));
    return clampi((int)r,-32768,32767);
}
__device__ __forceinline__ void rms_pair(int x0,int x1,int g0,int g1,int& y0,int& y1){
    int ss = x0*x0 + x1*x1;
    #pragma unroll
    for(int o=16;o>0;o>>=1) ss += __shfl_xor_sync(0xffffffffu, ss, o);
    int mean_sq = ss >> 6;
    int lut = min(mean_sq >> 6, 255);
    float bc = (float)(lut*64 + 32);
    int inv = clampi((int)rintf(__fdiv_rn(16384.f, __fsqrt_rn(bc))), 0, 16383);
    int p0 = (x0*inv) >> 8, p1 = (x1*inv) >> 8;
    y0 = clampi((int)floorf(__fmul_rn(__fmul_rn((float)p0,(float)g0), 0.0009765625f)),-128,127);
    y1 = clampi((int)floorf(__fmul_rn(__fmul_rn((float)p1,(float)g1), 0.0009765625f)),-128,127);
}
__device__ __forceinline__ void mma_s8s8(int* d, const int* a, const int* b){
    asm("mma.sync.aligned.m16n8k32.row.col.s32.s8.s8.s32 "
        "{%0,%1,%2,%3},{%4,%5,%6,%7},{%8,%9},{%0,%1,%2,%3};"
        : "+r"(d[0]),"+r"(d[1]),"+r"(d[2]),"+r"(d[3])
        : "r"(a[0]),"r"(a[1]),"r"(a[2]),"r"(a[3]),"r"(b[0]),"r"(b[1]));
}
__device__ __forceinline__ void mma_s8u8(int* d, const int* a, const int* b){
    asm("mma.sync.aligned.m16n8k32.row.col.s32.s8.u8.s32 "
        "{%0,%1,%2,%3},{%4,%5,%6,%7},{%8,%9},{%0,%1,%2,%3};"
        : "+r"(d[0]),"+r"(d[1]),"+r"(d[2]),"+r"(d[3])
        : "r"(a[0]),"r"(a[1]),"r"(a[2]),"r"(a[3]),"r"(b[0]),"r"(b[1]));
}
__device__ __forceinline__ void mma_u8s8(int* d, const unsigned* a, const int* b){
    asm("mma.sync.aligned.m16n8k32.row.col.s32.u8.s8.s32 "
        "{%0,%1,%2,%3},{%4,%5,%6,%7},{%8,%9},{%0,%1,%2,%3};"
        : "+r"(d[0]),"+r"(d[1]),"+r"(d[2]),"+r"(d[3])
        : "r"(a[0]),"r"(a[1]),"r"(a[2]),"r"(a[3]),"r"(b[0]),"r"(b[1]));
}
__device__ __forceinline__ int ea_of_idx(int l){
    return (l<16) ? l : (l<21 ? 64+11*(l-21) : (l<=24 ? 256+64*(l-24) : 0));
}
__device__ __forceinline__ void score4(const int* d, int c0, int r0, int r8, int* s){
    s[0] = (int)floorf(__fmul_rn(__int2float_rn(d[0]*45), 0.00390625f));
    s[1] = (int)floorf(__fmul_rn(__int2float_rn(d[1]*45), 0.00390625f));
    s[2] = (int)floorf(__fmul_rn(__int2float_rn(d[2]*45), 0.00390625f));
    s[3] = (int)floorf(__fmul_rn(__int2float_rn(d[3]*45), 0.00390625f));
    if(c0   > r0) s[0] = -32767;
    if(c0+1 > r0) s[1] = -32767;
    if(c0   > r8) s[2] = -32767;
    if(c0+1 > r8) s[3] = -32767;
}

// ---------------- merged prep ----------------
__global__ void prep_all(const float* qw, const float* kw, const float* vw,
                         const float* ow, const float* up, const float* dn,
                         const float* tok_emb, const float* attn_nw,
                         const float* ff_nw, const float* fin_nw){
    int m = blockIdx.x;
    if(m < 24){
        const float* src; int8_t* dst; int n;
        if(m < 16){
            int l = m >> 2, wsel = m & 3; n = D*D;
            const float* bases[4] = {qw,kw,vw,ow};
            int8_t* dsts[4] = {g_wq,g_wk,g_wv,g_wo};
            src = bases[wsel] + l*n; dst = dsts[wsel] + l*n;
        } else if(m < 20){ int l=m-16; n=DFF*D; src=up+l*n; dst=g_wup+l*n; }
        else             { int l=m-20; n=D*DFF; src=dn+l*n; dst=g_wdn+l*n; }

        __shared__ float red[256];
        float s = 0.f;
        for(int i=threadIdx.x;i<n;i+=256) s += fabsf(src[i]);
        red[threadIdx.x]=s; __syncthreads();
        for(int o=128;o>0;o>>=1){ if(threadIdx.x<o) red[threadIdx.x]+=red[threadIdx.x+o]; __syncthreads(); }
        float scale = fmaxf(__fdiv_rn(red[0], (float)n), 1e-5f);
        for(int i=threadIdx.x;i<n;i+=256){
            float t = rintf(__fdiv_rn(src[i], scale));
            t = fminf(fmaxf(t,-1.f),1.f);
            dst[i] = (int8_t)(int)t;
        }
        return;
    }
    int i = (m-24)*256 + threadIdx.x;
    if(i < VOCAB*D){
        float r = rintf(__fmul_rn(tok_emb[i],1024.f));
        int q = clampi((int)r,-32768,32767);
        g_ehi[i] = (int8_t)(q >> 8);
        g_elo[i] = (uint8_t)(q & 0xff);
    }
    if(m == 24){
        int t=threadIdx.x;
        for(int j=t;j<NL*D;j+=256){
            g_gattn[j] = gammaq(attn_nw[j]);
            g_gff[j]   = gammaq(ff_nw[j]);
        }
        if(t<D) g_gfin[t] = gammaq(fin_nw[t]);
    }
}

// ---- qkv tail with caller-provided weight fragments ----
__device__ __forceinline__ void qkv_tail_pf(const uint8_t* sx2, uint8_t* shb, int layer,
                                            int bt0, int warp, int lane, int g, int tg,
                                            const int wqkv[3][2][2]){
    const int* gm = g_gattn + layer*D;
    #pragma unroll
    for(int t=0;t<2;t++){
        int tok = 2*warp + t;
        int x0 = (int)(int8_t)sx2[tok*68 + 2*lane];
        int x1 = (int)(int8_t)sx2[tok*68 + 2*lane+1];
        int y0,y1;
        rms_pair(x0,x1,gm[2*lane],gm[2*lane+1],y0,y1);
        shb[tok*68 + 2*lane]   = (uint8_t)(y0 & 0xff);
        shb[tok*68 + 2*lane+1] = (uint8_t)(y1 & 0xff);
    }
    __syncthreads();
    const int* shi = (const int*)shb;
    int a[2][4];
    #pragma unroll
    for(int kc=0;kc<2;kc++){
        a[kc][0] = shi[g*17     + kc*8 + tg];
        a[kc][1] = shi[(g+8)*17 + kc*8 + tg];
        a[kc][2] = shi[g*17     + kc*8 + 4 + tg];
        a[kc][3] = shi[(g+8)*17 + kc*8 + 4 + tg];
    }
    #pragma unroll
    for(int nt=0;nt<3;nt++){
        int d[4] = {0,0,0,0};
        #pragma unroll
        for(int kc=0;kc<2;kc++){
            int b[2] = { wqkv[nt][kc][0], wqkv[nt][kc][1] };
            mma_s8s8(d, a[kc], b);
        }
        int o0 = warp*8 + 2*tg;
        int v0 = clampi(d[0]>>6,-128,127), v1 = clampi(d[1]>>6,-128,127);
        int v2 = clampi(d[2]>>6,-128,127), v3 = clampi(d[3]>>6,-128,127);
        if(nt < 2){
            int8_t* dst = (nt==0) ? g_q : g_k;
            *(uint16_t*)(dst + (bt0+g)*64   + o0) = (uint16_t)((v0&0xff) | ((v1&0xff)<<8));
            *(uint16_t*)(dst + (bt0+g+8)*64 + o0) = (uint16_t)((v2&0xff) | ((v3&0xff)<<8));
        } else {
            int bt_a = bt0 + g, bt_b = bt0 + g + 8;
            int bsel = bt_a >> 10;
            int ta = bt_a & (T-1), tb = bt_b & (T-1);
            int hh = o0 >> 5, hd = o0 & 31;
            int8_t* vtb = g_vt + (bsel*2 + hh)*((T/4)*HD*4);
            vtb[(ta>>2)*128 + hd*4     + (ta&3)] = (int8_t)v0;
            vtb[(ta>>2)*128 + (hd+1)*4 + (ta&3)] = (int8_t)v1;
            vtb[(tb>>2)*128 + hd*4     + (tb&3)] = (int8_t)v2;
            vtb[(tb>>2)*128 + (hd+1)*4 + (tb&3)] = (int8_t)v3;
        }
    }
}

// load qkv weight fragments for (layer, warp, g, tg)
__device__ __forceinline__ void load_qkv_frags(int layer, int warp, int g, int tg,
                                               int wqkv[3][2][2]){
    const int* wq = (const int*)(g_wq + layer*D*D);
    const int* wk = (const int*)(g_wk + layer*D*D);
    const int* wv = (const int*)(g_wv + layer*D*D);
    int c = warp*8 + g;
    #pragma unroll
    for(int nt=0;nt<3;nt++){
        const int* wb = (nt==0) ? wq : (nt==1 ? wk : wv);
        #pragma unroll
        for(int kc=0;kc<2;kc++){
            wqkv[nt][kc][0] = wb[c*16 + kc*8 + tg];
            wqkv[nt][kc][1] = wb[c*16 + kc*8 + 4 + tg];
        }
    }
}

// ---------------- embed + qkv(0) ----------------
__global__ __launch_bounds__(256) void embed_qkv_kernel(const int* tokens,
                                                        const float* tok_emb,
                                                        const float* pos_emb){
    __shared__ uint8_t sx2[16*68];
    __shared__ uint8_t shb[16*68];
    int tid = threadIdx.x, warp = tid>>5, lane = tid&31;
    int g = lane>>2, tg = lane&3;
    int bt0 = blockIdx.x*16;
    int wqkv[3][2][2];
    load_qkv_frags(0, warp, g, tg, wqkv);
    for(int idx = tid; idx < 16*64; idx += 256){
        int bt = bt0 + (idx>>6), d = idx & 63;
        int t = bt & (T-1);
        int tok = tokens[bt];
        int tq = clampi((int)rintf(__fmul_rn(tok_emb[tok*D+d],1024.f)),-32768,32767);
        int pq = clampi((int)rintf(__fmul_rn(pos_emb[t*D+d],1024.f)),-32768,32767);
        int xv = wrap8((tq+pq) >> 3);
        g_x[bt*D + d] = (int8_t)xv;
        sx2[(idx>>6)*68 + d] = (uint8_t)(xv & 0xff);
    }
    __syncthreads();
    qkv_tail_pf(sx2, shb, 0, bt0, warp, lane, g, tg, wqkv);
}

// ---------------- attention (exact R12 version) ----------------
#define SPB_PITCH 1040

__global__ __launch_bounds__(256) void attn_fused_kernel(){
    __shared__ uint8_t sP[16*SPB_PITCH];
    __shared__ uint8_t plut[16*32];
    __shared__ int rowmax[16];
    __shared__ int rowsum[16];
    __shared__ int sred[16*36];

    int tid = threadIdx.x, warp = tid>>5, lane = tid&31;
    int g = lane>>2, tg = lane&3;
    int qt = gridDim.x - 1 - blockIdx.x;     // LPT
    int bh = blockIdx.y, b = bh>>1, h = bh&1;
    int qb = qt*16, base = b*T;
    int KN = qb + 16, nch = KN >> 3;
    int KNpad = (KN + 31) & ~31;

    if(tid < 16){ rowmax[tid] = INT_MIN; rowsum[tid] = 0; }
    __syncthreads();

    const int* qp = (const int*)g_q;
    int aq[4];
    aq[0] = qp[(base+qb+g)*16   + h*8 + tg];
    aq[1] = qp[(base+qb+g+8)*16 + h*8 + tg];
    aq[2] = qp[(base+qb+g)*16   + h*8 + 4 + tg];
    aq[3] = qp[(base+qb+g+8)*16 + h*8 + 4 + tg];
    const int* kp = (const int*)g_k;
    int r0 = qb + g, r8 = qb + g + 8;

    // ---- pass A: row maxima (ILP x2) ----
    {
        int mg = INT_MIN, mg8 = INT_MIN;
        for(int c = warp; c < nch; c += 16){
            int k0 = c*8;
            bool has2 = (c+8) < nch;
            int bv0[2] = { kp[(base+k0+g)*16 + h*8 + tg], kp[(base+k0+g)*16 + h*8 + 4 + tg] };
            int d0[4] = {0,0,0,0}, d1[4] = {0,0,0,0};
            mma_s8s8(d0, aq, bv0);
            if(has2){
                int k1 = k0 + 64;
                int bv1[2] = { kp[(base+k1+g)*16 + h*8 + tg], kp[(base+k1+g)*16 + h*8 + 4 + tg] };
                mma_s8s8(d1, aq, bv1);
            }
            int s0[4], s1[4];
            score4(d0, k0 + 2*tg, r0, r8, s0);
            mg  = max(mg,  max(s0[0],s0[1]));
            mg8 = max(mg8, max(s0[2],s0[3]));
            if(has2){
                score4(d1, k0 + 64 + 2*tg, r0, r8, s1);
                mg  = max(mg,  max(s1[0],s1[1]));
                mg8 = max(mg8, max(s1[2],s1[3]));
            }
        }
        mg  = max(mg,  __shfl_xor_sync(0xffffffffu, mg , 1));
        mg  = max(mg,  __shfl_xor_sync(0xffffffffu, mg , 2));
        mg8 = max(mg8, __shfl_xor_sync(0xffffffffu, mg8, 1));
        mg8 = max(mg8, __shfl_xor_sync(0xffffffffu, mg8, 2));
        if(tg == 0){
            atomicMax(&rowmax[g],   mg);
            atomicMax(&rowmax[g+8], mg8);
        }
    }
    __syncthreads();

    // ---- pass B: recompute -> idx bytes + ea-sums ----
    {
        int m_g = rowmax[g], m_g8 = rowmax[g+8];
        int ea_l = ea_of_idx(lane);
        int su_g = 0, su_g8 = 0;
        for(int c = warp; c < nch; c += 16){
            int k0 = c*8;
            bool has2 = (c+8) < nch;
            int bv0[2] = { kp[(base+k0+g)*16 + h*8 + tg], kp[(base+k0+g)*16 + h*8 + 4 + tg] };
            int d0[4] = {0,0,0,0}, d1[4] = {0,0,0,0};
            mma_s8s8(d0, aq, bv0);
            if(has2){
                int k1 = k0 + 64;
                int bv1[2] = { kp[(base+k1+g)*16 + h*8 + tg], kp[(base+k1+g)*16 + h*8 + 4 + tg] };
                mma_s8s8(d1, aq, bv1);
            }
            #pragma unroll
            for(int u=0;u<2;u++){
                if(u==1 && !has2) break;
                int* dd = u ? d1 : d0;
                int c0 = k0 + u*64 + 2*tg;
                int s[4];
                score4(dd, c0, r0, r8, s);
                int i0 = max(s[0] - m_g  + 24, 0);
                int i1 = max(s[1] - m_g  + 24, 0);
                int i2 = max(s[2] - m_g8 + 24, 0);
                int i3 = max(s[3] - m_g8 + 24, 0);
                su_g  += __shfl_sync(0xffffffffu, ea_l, i0) + __shfl_sync(0xffffffffu, ea_l, i1);
                su_g8 += __shfl_sync(0xffffffffu, ea_l, i2) + __shfl_sync(0xffffffffu, ea_l, i3);
                *(uint16_t*)&sP[g*SPB_PITCH + c0]     = (uint16_t)(i0 | (i1<<8));
                *(uint16_t*)&sP[(g+8)*SPB_PITCH + c0] = (uint16_t)(i2 | (i3<<8));
            }
        }
        su_g  += __shfl_xor_sync(0xffffffffu, su_g, 1);
        su_g  += __shfl_xor_sync(0xffffffffu, su_g, 2);
        su_g8 += __shfl_xor_sync(0xffffffffu, su_g8, 1);
        su_g8 += __shfl_xor_sync(0xffffffffu, su_g8, 2);
        if(tg == 0){
            atomicAdd(&rowsum[g],   su_g);
            atomicAdd(&rowsum[g+8], su_g8);
        }
    }
    if(KNpad > KN && tid < 64){
        int row = tid >> 2, wsel = tid & 3;
        *(unsigned*)&sP[row*SPB_PITCH + KN + wsel*4] = 0;
    }
    __syncthreads();

    // ---- per-row prob LUT ----
    for(int e = tid; e < 512; e += 256){
        int row = e>>5, l = e&31;
        int p = 0;
        if(l <= 24){
            int ea = ea_of_idx(l);
            if(ea > 0){
                float sf = (float)max(rowsum[row], 1);
                p = clampi((int)rintf(__fmul_rn(__fdiv_rn((float)ea, sf), 255.f)), 0, 255);
            }
        }
        plut[row*32 + l] = (uint8_t)p;
    }
    __syncthreads();

    // ---- idx -> prob, word-wise in place ----
    #pragma unroll
    for(int rr = 0; rr < 2; rr++){
        int r = 2*warp + rr;
        const uint8_t* pl = plut + r*32;
        for(int wd = lane; wd < (KNpad>>2); wd += 32){
            unsigned v = *(unsigned*)&sP[r*SPB_PITCH + wd*4];
            unsigned o =  (unsigned)pl[v & 31]
                       | ((unsigned)pl[(v>>8)  & 31] << 8)
                       | ((unsigned)pl[(v>>16) & 31] << 16)
                       | ((unsigned)pl[(v>>24) & 31] << 24);
            *(unsigned*)&sP[r*SPB_PITCH + wd*4] = o;
        }
    }
    __syncthreads();

    // ---- AV via u8 x s8 MMA ----
    int nt = warp & 3, half = warp >> 2;
    int dim = nt*8 + g;
    const int* vt = (const int*)(g_vt) + bh*((T/4)*HD);
    int dacc[4] = {0,0,0,0};
    int nch32 = KNpad >> 5;
    for(int c32 = half; c32 < nch32; c32 += 2){
        unsigned A[4];
        A[0] = *(unsigned*)&sP[g*SPB_PITCH     + c32*32 + tg*4];
        A[1] = *(unsigned*)&sP[(g+8)*SPB_PITCH + c32*32 + tg*4];
        A[2] = *(unsigned*)&sP[g*SPB_PITCH     + c32*32 + 16 + tg*4];
        A[3] = *(unsigned*)&sP[(g+8)*SPB_PITCH + c32*32 + 16 + tg*4];
        int Bv[2];
        Bv[0] = vt[(c32*8 + tg)*32 + dim];
        Bv[1] = vt[(c32*8 + 4 + tg)*32 + dim];
        mma_u8s8(dacc, A, Bv);
    }
    if(half == 1){
        sred[g*36     + nt*8 + 2*tg]     = dacc[0];
        sred[g*36     + nt*8 + 2*tg + 1] = dacc[1];
        sred[(g+8)*36 + nt*8 + 2*tg]     = dacc[2];
        sred[(g+8)*36 + nt*8 + 2*tg + 1] = dacc[3];
    }
    __syncthreads();
    if(half == 0){
        int v0 = dacc[0] + sred[g*36     + nt*8 + 2*tg];
        int v1 = dacc[1] + sred[g*36     + nt*8 + 2*tg + 1];
        int v2 = dacc[2] + sred[(g+8)*36 + nt*8 + 2*tg];
        int v3 = dacc[3] + sred[(g+8)*36 + nt*8 + 2*tg + 1];
        int o0 = wrap8(v0>>8)&0xff, o1 = wrap8(v1>>8)&0xff;
        int o2 = wrap8(v2>>8)&0xff, o3 = wrap8(v3>>8)&0xff;
        *(uint16_t*)(g_a + (base+qb+g)*64   + h*32 + nt*8 + 2*tg) = (uint16_t)(o0 | (o1<<8));
        *(uint16_t*)(g_a + (base+qb+g+8)*64 + h*32 + nt*8 + 2*tg) = (uint16_t)(o2 | (o3<<8));
    }
}

// ---------------- fused ffn (+qkv l+1) with full weight prefetch ----------------
__global__ __launch_bounds__(256) void ffn_qkv_kernel(int layer){
    __shared__ int      sa[16*17];
    __shared__ uint8_t  sxb[16*64];
    __shared__ uint8_t  shb[16*68];
    __shared__ uint8_t  sub[16*260];
    __shared__ uint8_t  sx2[16*68];
    int tid = threadIdx.x, warp = tid>>5, lane = tid&31;
    int g = lane>>2, tg = lane&3;
    int bt0 = blockIdx.x*16;
    int cW = warp*8 + g;
    int o0 = warp*8 + 2*tg;

    // ===== prefetch ALL weight fragments + residual words up front =====
    int wof[2][2], wuf[4][2][2], wdf[8][2], wqkv[3][2][2];
    int xr0, xr1, xr2, xr3;
    {
        const int* wo = (const int*)(g_wo + layer*D*D);
        #pragma unroll
        for(int kc=0;kc<2;kc++){
            wof[kc][0] = wo[cW*16 + kc*8 + tg];
            wof[kc][1] = wo[cW*16 + kc*8 + 4 + tg];
        }
        const int* wu = (const int*)(g_wup + layer*DFF*D);
        #pragma unroll
        for(int nt=0;nt<4;nt++){
            int c = warp*32 + nt*8 + g;
            #pragma unroll
            for(int kc=0;kc<2;kc++){
                wuf[nt][kc][0] = wu[c*16 + kc*8 + tg];
                wuf[nt][kc][1] = wu[c*16 + kc*8 + 4 + tg];
            }
        }
        const int* wd = (const int*)(g_wdn + layer*D*DFF);
        #pragma unroll
        for(int kc=0;kc<8;kc++){
            wdf[kc][0] = wd[cW*64 + kc*8 + tg];
            wdf[kc][1] = wd[cW*64 + kc*8 + 4 + tg];
        }
        if(layer + 1 < NL) load_qkv_frags(layer+1, warp, g, tg, wqkv);
        xr0 = (int)g_x[(bt0+g)*64 + o0];
        xr1 = (int)g_x[(bt0+g)*64 + o0+1];
        xr2 = (int)g_x[(bt0+g+8)*64 + o0];
        xr3 = (int)g_x[(bt0+g+8)*64 + o0+1];
    }

    {
        int tok = tid>>4, i = tid&15;
        sa[tok*17+i] = ((const int*)g_a)[(bt0+tok)*16 + i];
    }
    __syncthreads();

    {   // oproj + residual
        int a[2][4];
        #pragma unroll
        for(int kc=0;kc<2;kc++){
            a[kc][0] = sa[g*17     + kc*8 + tg];
            a[kc][1] = sa[(g+8)*17 + kc*8 + tg];
            a[kc][2] = sa[g*17     + kc*8 + 4 + tg];
            a[kc][3] = sa[(g+8)*17 + kc*8 + 4 + tg];
        }
        int d[4] = {0,0,0,0};
        #pragma unroll
        for(int kc=0;kc<2;kc++){
            int b[2] = { wof[kc][0], wof[kc][1] };
            mma_s8s8(d, a[kc], b);
        }
        int r0 = clampi(d[0]>>6,-128,127), r1 = clampi(d[1]>>6,-128,127);
        int r2 = clampi(d[2]>>6,-128,127), r3 = clampi(d[3]>>6,-128,127);
        sxb[g*64 + o0]       = (uint8_t)(wrap8(xr0 + r0) & 0xff);
        sxb[g*64 + o0+1]     = (uint8_t)(wrap8(xr1 + r1) & 0xff);
        sxb[(g+8)*64 + o0]   = (uint8_t)(wrap8(xr2 + r2) & 0xff);
        sxb[(g+8)*64 + o0+1] = (uint8_t)(wrap8(xr3 + r3) & 0xff);
    }
    __syncthreads();

    {   // ffn rmsnorm
        const int* gm = g_gff + layer*D;
        #pragma unroll
        for(int t=0;t<2;t++){
            int tok = 2*warp + t;
            int x0 = (int)(int8_t)sxb[tok*64 + 2*lane];
            int x1 = (int)(int8_t)sxb[tok*64 + 2*lane+1];
            int y0,y1;
            rms_pair(x0,x1,gm[2*lane],gm[2*lane+1],y0,y1);
            shb[tok*68 + 2*lane]   = (uint8_t)(y0 & 0xff);
            shb[tok*68 + 2*lane+1] = (uint8_t)(y1 & 0xff);
        }
    }
    __syncthreads();

    {   // up + relu
        const int* shi = (const int*)shb;
        int a[2][4];
        #pragma unroll
        for(int kc=0;kc<2;kc++){
            a[kc][0] = shi[g*17     + kc*8 + tg];
            a[kc][1] = shi[(g+8)*17 + kc*8 + tg];
            a[kc][2] = shi[g*17     + kc*8 + 4 + tg];
            a[kc][3] = shi[(g+8)*17 + kc*8 + 4 + tg];
        }
        #pragma unroll
        for(int nt=0;nt<4;nt++){
            int colb = warp*32 + nt*8;
            int d[4] = {0,0,0,0};
            #pragma unroll
            for(int kc=0;kc<2;kc++){
                int b[2] = { wuf[nt][kc][0], wuf[nt][kc][1] };
                mma_s8s8(d, a[kc], b);
            }
            int c0 = colb + 2*tg;
            int u0 = max(clampi(d[0]>>6,-128,127),0), u1 = max(clampi(d[1]>>6,-128,127),0);
            int u2 = max(clampi(d[2]>>6,-128,127),0), u3 = max(clampi(d[3]>>6,-128,127),0);
            sub[g*260 + c0]       = (uint8_t)u0;
            sub[g*260 + c0+1]     = (uint8_t)u1;
            sub[(g+8)*260 + c0]   = (uint8_t)u2;
            sub[(g+8)*260 + c0+1] = (uint8_t)u3;
        }
    }
    __syncthreads();

    {   // down (K=256) + residual -> sx2, g_x
        const int* sui = (const int*)sub;
        int d[4] = {0,0,0,0};
        #pragma unroll
        for(int kc=0;kc<8;kc++){
            int a[4];
            a[0] = sui[g*65     + kc*8 + tg];
            a[1] = sui[(g+8)*65 + kc*8 + tg];
            a[2] = sui[g*65     + kc*8 + 4 + tg];
            a[3] = sui[(g+8)*65 + kc*8 + 4 + tg];
            int b[2] = { wdf[kc][0], wdf[kc][1] };
            mma_s8s8(d, a, b);
        }
        int r0 = clampi(d[0]>>6,-128,127), r1 = clampi(d[1]>>6,-128,127);
        int r2 = clampi(d[2]>>6,-128,127), r3 = clampi(d[3]>>6,-128,127);
        int x0 = wrap8((int)(int8_t)sxb[g*64 + o0]       + r0);
        int x1 = wrap8((int)(int8_t)sxb[g*64 + o0+1]     + r1);
        int x2 = wrap8((int)(int8_t)sxb[(g+8)*64 + o0]   + r2);
        int x3 = wrap8((int)(int8_t)sxb[(g+8)*64 + o0+1] + r3);
        g_x[(bt0+g)*64 + o0]     = (int8_t)x0;
        g_x[(bt0+g)*64 + o0+1]   = (int8_t)x1;
        g_x[(bt0+g+8)*64 + o0]   = (int8_t)x2;
        g_x[(bt0+g+8)*64 + o0+1] = (int8_t)x3;
        sx2[g*68 + o0]       = (uint8_t)(x0 & 0xff);
        sx2[g*68 + o0+1]     = (uint8_t)(x1 & 0xff);
        sx2[(g+8)*68 + o0]   = (uint8_t)(x2 & 0xff);
        sx2[(g+8)*68 + o0+1] = (uint8_t)(x3 & 0xff);
    }
    __syncthreads();

    if(layer + 1 < NL){
        qkv_tail_pf(sx2, shb, layer+1, bt0, warp, lane, g, tg, wqkv);
    } else {
        const int* gm = g_gfin;
        #pragma unroll
        for(int t=0;t<2;t++){
            int tok = 2*warp + t;
            int x0 = (int)(int8_t)sx2[tok*68 + 2*lane];
            int x1 = (int)(int8_t)sx2[tok*68 + 2*lane+1];
            int y0,y1;
            rms_pair(x0,x1,gm[2*lane],gm[2*lane+1],y0,y1);
            g_h[(bt0+tok)*D + 2*lane]   = (int8_t)y0;
            g_h[(bt0+tok)*D + 2*lane+1] = (int8_t)y1;
        }
    }
}

// ---------------- logits via IMMA ----------------
__global__ __launch_bounds__(256) void logits_mma_kernel(float* __restrict__ out){
    int warp = threadIdx.x>>5, lane = threadIdx.x&31;
    int g = lane>>2, tg = lane&3;
    int vbase = blockIdx.x*256 + warp*32;
    int mbase = blockIdx.y*64;

    int bhi[4][2][2], blo[4][2][2];
    #pragma unroll
    for(int nt=0;nt<4;nt++){
        int col = vbase + nt*8 + g;
        const int8_t*  eh = g_ehi + col*64;
        const uint8_t* el = g_elo + col*64;
        #pragma unroll
        for(int kc=0;kc<2;kc++){
            bhi[nt][kc][0] = *(const int*)(eh + kc*32 + tg*4);
            bhi[nt][kc][1] = *(const int*)(eh + kc*32 + 16 + tg*4);
            blo[nt][kc][0] = *(const int*)(el + kc*32 + tg*4);
            blo[nt][kc][1] = *(const int*)(el + kc*32 + 16 + tg*4);
        }
    }
    #pragma unroll
    for(int mt=0;mt<4;mt++){
        int row0 = mbase + mt*16 + g;
        const int8_t* h0 = g_h + row0*64;
        const int8_t* h8 = g_h + (row0+8)*64;
        int a[2][4];
        #pragma unroll
        for(int kc=0;kc<2;kc++){
            a[kc][0] = *(const int*)(h0 + kc*32 + tg*4);
            a[kc][1] = *(const int*)(h8 + kc*32 + tg*4);
            a[kc][2] = *(const int*)(h0 + kc*32 + 16 + tg*4);
            a[kc][3] = *(const int*)(h8 + kc*32 + 16 + tg*4);
        }
        #pragma unroll
        for(int nt=0;nt<4;nt++){
            int dh[4]={0,0,0,0}, dl[4]={0,0,0,0};
            #pragma unroll
            for(int kc=0;kc<2;kc++){
                mma_s8s8(dh, a[kc], bhi[nt][kc]);
                mma_s8u8(dl, a[kc], blo[nt][kc]);
            }
            int col = vbase + nt*8 + 2*tg;
            float2 v0, v1;
            v0.x = __fmul_rn((float)(dh[0]*256+dl[0]), 1.220703125e-4f);
            v0.y = __fmul_rn((float)(dh[1]*256+dl[1]), 1.220703125e-4f);
            v1.x = __fmul_rn((float)(dh[2]*256+dl[2]), 1.220703125e-4f);
            v1.y = __fmul_rn((float)(dh[3]*256+dl[3]), 1.220703125e-4f);
            *(float2*)(out + (size_t)row0*VOCAB + col)     = v0;
            *(float2*)(out + (size_t)(row0+8)*VOCAB + col) = v1;
        }
    }
}

// ---------------- launch ----------------
extern "C" void kernel_launch(void* const* d_in, const int* in_sizes, int n_in,
                              void* d_out, int out_size){
    const int*   tokens  = (const int*)  d_in[0];
    const float* tok_emb = (const float*)d_in[1];
    const float* pos_emb = (const float*)d_in[2];
    const float* attn_nw = (const float*)d_in[3];
    const float* qw      = (const float*)d_in[4];
    const float* kw      = (const float*)d_in[5];
    const float* vw      = (const float*)d_in[6];
    const float* ow      = (const float*)d_in[7];
    const float* ff_nw   = (const float*)d_in[8];
    const float* up      = (const float*)d_in[9];
    const float* dn      = (const float*)d_in[10];
    const float* fin_nw  = (const float*)d_in[11];
    float* out = (float*)d_out;

    prep_all<<<24 + (VOCAB*D+255)/256, 256>>>(qw,kw,vw,ow,up,dn,
                                              tok_emb, attn_nw, ff_nw, fin_nw);
    embed_qkv_kernel<<<BT/16,256>>>(tokens, tok_emb, pos_emb);

    for(int l=0;l<NL;l++){
        attn_fused_kernel<<<dim3(T/16, BATCH*H),256>>>();
        ffn_qkv_kernel<<<BT/16,256>>>(l);
    }
    logits_mma_kernel<<<dim3(VOCAB/256, BT/64),256>>>(out);
}